// round 14
// baseline (speedup 1.0000x reference)
#include <cuda_runtime.h>
#include <math.h>
#include <stdint.h>

#define HH 128
#define WW 128
#define BB 8
#define CIN 64
#define COUT 64
#define HW (HH*WW)
#define NCH 27            // 18 offset channels + 9 mask channels
#define NPAIR 7
#define CSTR 68           // colT row stride in floats

// scratch (allocation-free: device globals)
__device__ float g_om[BB*NCH*HW];     // offsets + mask=2*sigmoid
__device__ float g_wT[9*64*64];       // [tap][cin][oc]
__device__ int   g_flag[BB*64];       // per (b, row-pair) completion count (0..2)

#define CONV_BLOCKS 1024              // (64 hp) x (8 b) x (2 z)
#define DEF_BLOCKS  2048              // (8 b) x (128 h) x (2 wb)
#define FSM_BYTES 34816               // max(conv 34816, deform 17408)

// ---------------------------------------------------------------------------
// packed fp32x2 helpers
// ---------------------------------------------------------------------------
__device__ __forceinline__ uint64_t pack2(float lo, float hi) {
    uint64_t r;
    asm("mov.b64 %0, {%1,%2};" : "=l"(r)
        : "r"(__float_as_uint(lo)), "r"(__float_as_uint(hi)));
    return r;
}
__device__ __forceinline__ void unpack2(uint64_t v, float& lo, float& hi) {
    uint32_t a, b;
    asm("mov.b64 {%0,%1}, %2;" : "=r"(a), "=r"(b) : "l"(v));
    lo = __uint_as_float(a); hi = __uint_as_float(b);
}
#define FFMA2(acc, a, b) \
    asm("fma.rn.f32x2 %0, %1, %2, %0;" : "+l"(acc) : "l"(a), "l"(b))

// ---------------------------------------------------------------------------
// Kernel 0: weight transform [oc][c][3][3] -> g_wT[t][c][oc]
// ---------------------------------------------------------------------------
__global__ void transpose_w_kernel(const float* __restrict__ w) {
    int idx = blockIdx.x * 256 + threadIdx.x;
    if (idx < 576 * COUT) {
        int oc  = idx / 576;
        int rem = idx % 576;
        int c   = rem / 9;
        int t   = rem % 9;
        g_wT[t * 4096 + c * 64 + oc] = w[idx];
    }
}

// ---------------------------------------------------------------------------
// Conv role (R7 inner code, measured 105.9us standalone). Unchanged.
// ---------------------------------------------------------------------------
__device__ __forceinline__ void conv_role(
    char* sm, int b, int c,
    const float* __restrict__ data,
    const float* __restrict__ w_off, const float* __restrict__ b_off,
    const float* __restrict__ w_mod, const float* __restrict__ b_mod)
{
    uint64_t* wsp   = (uint64_t*)sm;                 // 17920 B
    float*    dtile = (float*)(sm + 17920);          // 16896 B

    const int hp = c & 63;
    const int pb = (c >> 6) * NPAIR;                 // pair base (0 or 7)
    const int h0 = hp * 2;
    const int x  = threadIdx.x;

    if (threadIdx.x < 64) {
        int q = threadIdx.x >> 3;
        int r = (threadIdx.x >> 1) & 3;
        int s = threadIdx.x & 1;
        dtile[q * 528 + r * 132 + s * 129] = 0.0f;
    }

    uint64_t acc2[2][NPAIR];
#pragma unroll
    for (int p = 0; p < NPAIR; p++) {
        int ocA = 2 * (pb + p), ocB = ocA + 1;
        float bA = (ocA < 18) ? b_off[ocA] : b_mod[ocA - 18];
        float bB = (ocB < 18) ? b_off[ocB] : ((ocB < 27) ? b_mod[ocB - 18] : 0.0f);
        acc2[0][p] = pack2(bA, bB);
        acc2[1][p] = acc2[0][p];
    }

    for (int c0 = 0; c0 < CIN; c0 += 32) {
        __syncthreads();
        for (int idx = threadIdx.x; idx < NPAIR * 32 * 9; idx += 128) {
            int p  = idx / 288;
            int r  = idx % 288;
            int cc = r / 9;
            int k  = r % 9;
            int ocA = 2 * (pb + p), ocB = ocA + 1;
            const float* sA = (ocA < 18) ? (w_off + ocA * 576) : (w_mod + (ocA - 18) * 576);
            float vA = sA[(c0 + cc) * 9 + k];
            float vB = 0.0f;
            if (ocB < 27) {
                const float* sB = (ocB < 18) ? (w_off + ocB * 576) : (w_mod + (ocB - 18) * 576);
                vB = sB[(c0 + cc) * 9 + k];
            }
            wsp[(p * 32 + cc) * 10 + k] = pack2(vA, vB);
        }

        for (int cg = 0; cg < 4; cg++) {
            __syncthreads();
            const int cb = c0 + cg * 8;
#pragma unroll
            for (int q = 0; q < 8; q++) {
                const float* dp = data + ((size_t)(b * CIN + cb + q)) * HW;
#pragma unroll
                for (int r = 0; r < 4; r++) {
                    int hy = h0 - 1 + r;
                    float v = 0.0f;
                    if (hy >= 0 && hy < HH) v = dp[hy * WW + x];
                    dtile[q * 528 + r * 132 + 1 + x] = v;
                }
            }
            __syncthreads();

#pragma unroll
            for (int q = 0; q < 8; q++) {
                const int cc = cg * 8 + q;
                const float* dp = dtile + q * 528 + x;
                uint64_t dup[4][3];
#pragma unroll
                for (int r = 0; r < 4; r++)
#pragma unroll
                    for (int kx = 0; kx < 3; kx++) {
                        float v = dp[r * 132 + kx];
                        dup[r][kx] = pack2(v, v);
                    }

#pragma unroll
                for (int p = 0; p < NPAIR; p++) {
                    const uint64_t* base = wsp + (p * 32 + cc) * 10;
                    ulonglong2 w01 = *(const ulonglong2*)(base + 0);
                    ulonglong2 w23 = *(const ulonglong2*)(base + 2);
                    ulonglong2 w45 = *(const ulonglong2*)(base + 4);
                    ulonglong2 w67 = *(const ulonglong2*)(base + 6);
                    uint64_t   w8  = base[8];
                    FFMA2(acc2[0][p], dup[0][0], w01.x);
                    FFMA2(acc2[0][p], dup[0][1], w01.y);
                    FFMA2(acc2[0][p], dup[0][2], w23.x);
                    FFMA2(acc2[0][p], dup[1][0], w23.y);
                    FFMA2(acc2[0][p], dup[1][1], w45.x);
                    FFMA2(acc2[0][p], dup[1][2], w45.y);
                    FFMA2(acc2[0][p], dup[2][0], w67.x);
                    FFMA2(acc2[0][p], dup[2][1], w67.y);
                    FFMA2(acc2[0][p], dup[2][2], w8);
                    FFMA2(acc2[1][p], dup[1][0], w01.x);
                    FFMA2(acc2[1][p], dup[1][1], w01.y);
                    FFMA2(acc2[1][p], dup[1][2], w23.x);
                    FFMA2(acc2[1][p], dup[2][0], w23.y);
                    FFMA2(acc2[1][p], dup[2][1], w45.x);
                    FFMA2(acc2[1][p], dup[2][2], w45.y);
                    FFMA2(acc2[1][p], dup[3][0], w67.x);
                    FFMA2(acc2[1][p], dup[3][1], w67.y);
                    FFMA2(acc2[1][p], dup[3][2], w8);
                }
            }
        }
    }

#pragma unroll
    for (int rr = 0; rr < 2; rr++) {
        float* outp = g_om + ((size_t)(b * NCH) * HH + (h0 + rr)) * WW + x;
#pragma unroll
        for (int p = 0; p < NPAIR; p++) {
            float lo, hi;
            unpack2(acc2[rr][p], lo, hi);
            int ocA = 2 * (pb + p), ocB = ocA + 1;
            if (ocA >= 18) lo = 2.0f / (1.0f + expf(-lo));
            outp[ocA * HW] = lo;
            if (ocB < 27) {
                if (ocB >= 18) hi = 2.0f / (1.0f + expf(-hi));
                outp[ocB * HW] = hi;
            }
        }
    }

    __syncthreads();
    __threadfence();
    if (threadIdx.x == 0) atomicAdd(&g_flag[b * 64 + hp], 1);
}

// ---------------------------------------------------------------------------
// Deform role: 64-px blocks (R11 shape, ~90 regs -> 5 blocks/SM), weights
// read directly from g_wT via LDG.128 (no wsm staging). smem = colT 17408B.
// ---------------------------------------------------------------------------
__device__ __forceinline__ void deform_role(
    char* sm, int b, int d,
    const float* __restrict__ data,
    const float* __restrict__ bias,
    float* __restrict__ out)
{
    float* colT = (float*)sm;                  // [64][CSTR] 17408 B

    const int h   = d >> 1;
    const int w0  = (d & 1) * 64;
    const int tid = threadIdx.x;

    // ---- wait for this row's offsets/masks ----
    if (tid == 0) {
        int* fp = &g_flag[b * 64 + (h >> 1)];
        while (atomicAdd(fp, 0) < 2) { __nanosleep(200); }
    }
    __syncthreads();
    __threadfence();

    const float* dbase = data + (size_t)b * CIN * HW;
    const float* omb   = g_om + ((size_t)(b * NCH) * HH + h) * WW;

    const int i   = tid >> 4;            // oc group (0..7)
    const int j   = tid & 15;            // px group (0..15)
    const int oc0 = i * 8;

    const int gp = tid & 63;             // gather pixel
    const int gc = (tid >> 6) * 32;      // gather channel base
    const int x  = w0 + gp;

    uint64_t acc[4][4];                  // [oc pair][px]
#pragma unroll
    for (int p = 0; p < 4; p++)
#pragma unroll
        for (int q = 0; q < 4; q++) acc[p][q] = 0ULL;

    for (int t = 0; t < 9; t++) {
        __syncthreads();                 // prev GEMM done before overwrite

        // ---- bilinear metadata for this thread's pixel ----
        const float dy = omb[(2 * t) * HW + x];
        const float dx = omb[(2 * t + 1) * HW + x];
        const float mk = omb[(18 + t) * HW + x];

        const float py = (float)(h - 1 + t / 3) + dy;
        const float px = (float)(x - 1 + t % 3) + dx;

        const float y0f = floorf(py), x0f = floorf(px);
        const float wy1 = py - y0f,  wx1 = px - x0f;
        const float wy0 = 1.0f - wy1, wx0 = 1.0f - wx1;

        const int y0 = (int)y0f, x0 = (int)x0f;
        const int y1 = y0 + 1,   x1 = x0 + 1;
        const bool vy0 = (y0 >= 0) && (y0 < HH);
        const bool vy1 = (y1 >= 0) && (y1 < HH);
        const bool vx0 = (x0 >= 0) && (x0 < WW);
        const bool vx1 = (x1 >= 0) && (x1 < WW);

        const float w00 = (vy0 && vx0) ? mk * wy0 * wx0 : 0.0f;
        const float w01 = (vy0 && vx1) ? mk * wy0 * wx1 : 0.0f;
        const float w10 = (vy1 && vx0) ? mk * wy1 * wx0 : 0.0f;
        const float w11 = (vy1 && vx1) ? mk * wy1 * wx1 : 0.0f;

        const int yc0 = min(max(y0, 0), HH - 1);
        const int yc1 = min(max(y1, 0), HH - 1);
        const int xc0 = min(max(x0, 0), WW - 1);
        const int xc1 = min(max(x1, 0), WW - 1);
        const int i00 = yc0 * WW + xc0;
        const int i01 = yc0 * WW + xc1;
        const int i10 = yc1 * WW + xc0;
        const int i11 = yc1 * WW + xc1;

        // ---- gather 32 channels for this pixel ----
        const float* d2 = dbase + (size_t)gc * HW;
        float* cp = colT + gc * CSTR + gp;
#pragma unroll 8
        for (int cc = 0; cc < 32; cc++) {
            float v = w00 * d2[i00];
            v = fmaf(w01, d2[i01], v);
            v = fmaf(w10, d2[i10], v);
            v = fmaf(w11, d2[i11], v);
            cp[cc * CSTR] = v;
            d2 += HW;
        }
        __syncthreads();

        // ---- GEMM: 64 k; weights streamed via LDG.128 (L1/L2 hot) ----
        const float* wg   = g_wT + t * 4096 + oc0;
        const float* crow = colT + j * 4;
#pragma unroll 8
        for (int kl = 0; kl < 64; kl++) {
            ulonglong2 wA = *(const ulonglong2*)(wg + kl * 64);      // oc 0-3
            ulonglong2 wB = *(const ulonglong2*)(wg + kl * 64 + 4);  // oc 4-7
            float4 cv = *(const float4*)(crow + kl * CSTR);          // px j4..j4+3
            uint64_t c0 = pack2(cv.x, cv.x);
            uint64_t c1 = pack2(cv.y, cv.y);
            uint64_t c2 = pack2(cv.z, cv.z);
            uint64_t c3 = pack2(cv.w, cv.w);
            FFMA2(acc[0][0], wA.x, c0); FFMA2(acc[0][1], wA.x, c1);
            FFMA2(acc[0][2], wA.x, c2); FFMA2(acc[0][3], wA.x, c3);
            FFMA2(acc[1][0], wA.y, c0); FFMA2(acc[1][1], wA.y, c1);
            FFMA2(acc[1][2], wA.y, c2); FFMA2(acc[1][3], wA.y, c3);
            FFMA2(acc[2][0], wB.x, c0); FFMA2(acc[2][1], wB.x, c1);
            FFMA2(acc[2][2], wB.x, c2); FFMA2(acc[2][3], wB.x, c3);
            FFMA2(acc[3][0], wB.y, c0); FFMA2(acc[3][1], wB.y, c1);
            FFMA2(acc[3][2], wB.y, c2); FFMA2(acc[3][3], wB.y, c3);
        }
    }

    // ---- epilogue: bias + relu + float4 stores ----
#pragma unroll
    for (int p = 0; p < 4; p++) {
        const int ocA = oc0 + 2 * p;
        const float bA = bias[ocA];
        const float bB = bias[ocA + 1];
        float a0, b0, a1, b1, a2, b2, a3, b3;
        unpack2(acc[p][0], a0, b0);
        unpack2(acc[p][1], a1, b1);
        unpack2(acc[p][2], a2, b2);
        unpack2(acc[p][3], a3, b3);
        float* obA = out + (((size_t)(b * COUT + ocA)) * HH + h) * WW + w0 + j * 4;
        float4 rA = make_float4(fmaxf(a0 + bA, 0.f), fmaxf(a1 + bA, 0.f),
                                fmaxf(a2 + bA, 0.f), fmaxf(a3 + bA, 0.f));
        *(float4*)obA = rA;
        float4 rB = make_float4(fmaxf(b0 + bB, 0.f), fmaxf(b1 + bB, 0.f),
                                fmaxf(b2 + bB, 0.f), fmaxf(b3 + bB, 0.f));
        *(float4*)(obA + HW) = rB;
    }
}

// ---------------------------------------------------------------------------
// Fused kernel: bids [0,1024) conv, [1024,3072) deform. Natural order.
// ---------------------------------------------------------------------------
__global__ void __launch_bounds__(128, 5) fused_kernel(
    const float* __restrict__ data,
    const float* __restrict__ w_off, const float* __restrict__ b_off,
    const float* __restrict__ w_mod, const float* __restrict__ b_mod,
    const float* __restrict__ bias,
    float* __restrict__ out)
{
    extern __shared__ char sm[];
    const int bid = blockIdx.x;
    if (bid < CONV_BLOCKS) {
        const int hp = bid & 63;
        const int b  = (bid >> 6) & 7;
        const int z  = bid >> 9;
        conv_role(sm, b, hp | (z << 6), data, w_off, b_off, w_mod, b_mod);
    } else {
        const int idx = bid - CONV_BLOCKS;
        deform_role(sm, idx >> 8, idx & 255, data, bias, out);
    }
}

// ---------------------------------------------------------------------------
extern "C" void kernel_launch(void* const* d_in, const int* in_sizes, int n_in,
                              void* d_out, int out_size)
{
    const float* data  = (const float*)d_in[0];
    const float* w     = (const float*)d_in[1];
    const float* bias  = (const float*)d_in[2];
    const float* w_off = (const float*)d_in[3];
    const float* b_off = (const float*)d_in[4];
    const float* w_mod = (const float*)d_in[5];
    const float* b_mod = (const float*)d_in[6];
    float* out = (float*)d_out;

    void* flag_ptr = nullptr;
    cudaGetSymbolAddress(&flag_ptr, g_flag);
    cudaMemsetAsync(flag_ptr, 0, BB * 64 * sizeof(int));

    cudaFuncSetAttribute(fused_kernel,
                         cudaFuncAttributeMaxDynamicSharedMemorySize, FSM_BYTES);

    transpose_w_kernel<<<144, 256>>>(w);
    fused_kernel<<<CONV_BLOCKS + DEF_BLOCKS, 128, FSM_BYTES>>>(
        data, w_off, b_off, w_mod, b_mod, bias, out);
}

// round 15
// speedup vs baseline: 1.1784x; 1.1784x over previous
#include <cuda_runtime.h>
#include <math.h>
#include <stdint.h>

#define HH 128
#define WW 128
#define BB 8
#define CIN 64
#define COUT 64
#define HW (HH*WW)
#define NCH 27            // 18 offset channels + 9 mask channels
#define NPAIR 7
#define CST2 132          // colT row stride in floats (128 + 4 pad)

// scratch (allocation-free: device globals)
__device__ float g_om[BB*NCH*HW];     // offsets + mask=2*sigmoid
__device__ float g_wT[9*64*64];       // [tap][cin][oc]
__device__ int   g_flag[BB*64];       // per (b, row-pair) completion count (0..2)

#define CONV_BLOCKS 1024              // (64 hp) x (8 b) x (2 z)
#define DEF_BLOCKS  1024              // (8 b) x (128 h), full row per block
#define FSM_BYTES 50176               // max(conv 34816, deform 16384+33792)

// ---------------------------------------------------------------------------
// packed fp32x2 helpers
// ---------------------------------------------------------------------------
__device__ __forceinline__ uint64_t pack2(float lo, float hi) {
    uint64_t r;
    asm("mov.b64 %0, {%1,%2};" : "=l"(r)
        : "r"(__float_as_uint(lo)), "r"(__float_as_uint(hi)));
    return r;
}
__device__ __forceinline__ void unpack2(uint64_t v, float& lo, float& hi) {
    uint32_t a, b;
    asm("mov.b64 {%0,%1}, %2;" : "=r"(a), "=r"(b) : "l"(v));
    lo = __uint_as_float(a); hi = __uint_as_float(b);
}
#define FFMA2(acc, a, b) \
    asm("fma.rn.f32x2 %0, %1, %2, %0;" : "+l"(acc) : "l"(a), "l"(b))

// ---------------------------------------------------------------------------
// Kernel 0: weight transform [oc][c][3][3] -> g_wT[t][c][oc]
// ---------------------------------------------------------------------------
__global__ void transpose_w_kernel(const float* __restrict__ w) {
    int idx = blockIdx.x * 256 + threadIdx.x;
    if (idx < 576 * COUT) {
        int oc  = idx / 576;
        int rem = idx % 576;
        int c   = rem / 9;
        int t   = rem % 9;
        g_wT[t * 4096 + c * 64 + oc] = w[idx];
    }
}

// ---------------------------------------------------------------------------
// Conv role (R7 inner code, measured 105.9us standalone). Unchanged.
// ---------------------------------------------------------------------------
__device__ __forceinline__ void conv_role(
    char* sm, int b, int c,
    const float* __restrict__ data,
    const float* __restrict__ w_off, const float* __restrict__ b_off,
    const float* __restrict__ w_mod, const float* __restrict__ b_mod)
{
    uint64_t* wsp   = (uint64_t*)sm;                 // 17920 B
    float*    dtile = (float*)(sm + 17920);          // 16896 B

    const int hp = c & 63;
    const int pb = (c >> 6) * NPAIR;                 // pair base (0 or 7)
    const int h0 = hp * 2;
    const int x  = threadIdx.x;

    if (threadIdx.x < 64) {
        int q = threadIdx.x >> 3;
        int r = (threadIdx.x >> 1) & 3;
        int s = threadIdx.x & 1;
        dtile[q * 528 + r * 132 + s * 129] = 0.0f;
    }

    uint64_t acc2[2][NPAIR];
#pragma unroll
    for (int p = 0; p < NPAIR; p++) {
        int ocA = 2 * (pb + p), ocB = ocA + 1;
        float bA = (ocA < 18) ? b_off[ocA] : b_mod[ocA - 18];
        float bB = (ocB < 18) ? b_off[ocB] : ((ocB < 27) ? b_mod[ocB - 18] : 0.0f);
        acc2[0][p] = pack2(bA, bB);
        acc2[1][p] = acc2[0][p];
    }

    for (int c0 = 0; c0 < CIN; c0 += 32) {
        __syncthreads();
        for (int idx = threadIdx.x; idx < NPAIR * 32 * 9; idx += 128) {
            int p  = idx / 288;
            int r  = idx % 288;
            int cc = r / 9;
            int k  = r % 9;
            int ocA = 2 * (pb + p), ocB = ocA + 1;
            const float* sA = (ocA < 18) ? (w_off + ocA * 576) : (w_mod + (ocA - 18) * 576);
            float vA = sA[(c0 + cc) * 9 + k];
            float vB = 0.0f;
            if (ocB < 27) {
                const float* sB = (ocB < 18) ? (w_off + ocB * 576) : (w_mod + (ocB - 18) * 576);
                vB = sB[(c0 + cc) * 9 + k];
            }
            wsp[(p * 32 + cc) * 10 + k] = pack2(vA, vB);
        }

        for (int cg = 0; cg < 4; cg++) {
            __syncthreads();
            const int cb = c0 + cg * 8;
#pragma unroll
            for (int q = 0; q < 8; q++) {
                const float* dp = data + ((size_t)(b * CIN + cb + q)) * HW;
#pragma unroll
                for (int r = 0; r < 4; r++) {
                    int hy = h0 - 1 + r;
                    float v = 0.0f;
                    if (hy >= 0 && hy < HH) v = dp[hy * WW + x];
                    dtile[q * 528 + r * 132 + 1 + x] = v;
                }
            }
            __syncthreads();

#pragma unroll
            for (int q = 0; q < 8; q++) {
                const int cc = cg * 8 + q;
                const float* dp = dtile + q * 528 + x;
                uint64_t dup[4][3];
#pragma unroll
                for (int r = 0; r < 4; r++)
#pragma unroll
                    for (int kx = 0; kx < 3; kx++) {
                        float v = dp[r * 132 + kx];
                        dup[r][kx] = pack2(v, v);
                    }

#pragma unroll
                for (int p = 0; p < NPAIR; p++) {
                    const uint64_t* base = wsp + (p * 32 + cc) * 10;
                    ulonglong2 w01 = *(const ulonglong2*)(base + 0);
                    ulonglong2 w23 = *(const ulonglong2*)(base + 2);
                    ulonglong2 w45 = *(const ulonglong2*)(base + 4);
                    ulonglong2 w67 = *(const ulonglong2*)(base + 6);
                    uint64_t   w8  = base[8];
                    FFMA2(acc2[0][p], dup[0][0], w01.x);
                    FFMA2(acc2[0][p], dup[0][1], w01.y);
                    FFMA2(acc2[0][p], dup[0][2], w23.x);
                    FFMA2(acc2[0][p], dup[1][0], w23.y);
                    FFMA2(acc2[0][p], dup[1][1], w45.x);
                    FFMA2(acc2[0][p], dup[1][2], w45.y);
                    FFMA2(acc2[0][p], dup[2][0], w67.x);
                    FFMA2(acc2[0][p], dup[2][1], w67.y);
                    FFMA2(acc2[0][p], dup[2][2], w8);
                    FFMA2(acc2[1][p], dup[1][0], w01.x);
                    FFMA2(acc2[1][p], dup[1][1], w01.y);
                    FFMA2(acc2[1][p], dup[1][2], w23.x);
                    FFMA2(acc2[1][p], dup[2][0], w23.y);
                    FFMA2(acc2[1][p], dup[2][1], w45.x);
                    FFMA2(acc2[1][p], dup[2][2], w45.y);
                    FFMA2(acc2[1][p], dup[3][0], w67.x);
                    FFMA2(acc2[1][p], dup[3][1], w67.y);
                    FFMA2(acc2[1][p], dup[3][2], w8);
                }
            }
        }
    }

#pragma unroll
    for (int rr = 0; rr < 2; rr++) {
        float* outp = g_om + ((size_t)(b * NCH) * HH + (h0 + rr)) * WW + x;
#pragma unroll
        for (int p = 0; p < NPAIR; p++) {
            float lo, hi;
            unpack2(acc2[rr][p], lo, hi);
            int ocA = 2 * (pb + p), ocB = ocA + 1;
            if (ocA >= 18) lo = 2.0f / (1.0f + expf(-lo));
            outp[ocA * HW] = lo;
            if (ocB < 27) {
                if (ocB >= 18) hi = 2.0f / (1.0f + expf(-hi));
                outp[ocB * HW] = hi;
            }
        }
    }

    __syncthreads();
    __threadfence();
    if (threadIdx.x == 0) atomicAdd(&g_flag[b * 64 + hp], 1);
}

// ---------------------------------------------------------------------------
// Deform role: full 128-px row per block (halved weight traffic), weights
// staged in smem per tap (29cyc LDS in inner loop, no L2-latency LDG).
// smem = wsm 16KB + colT 33.8KB = 49.8KB -> 4 blocks/SM (regs 128 = RF cap).
// ---------------------------------------------------------------------------
__device__ __forceinline__ void deform_role(
    char* sm, int b, int h,
    const float* __restrict__ data,
    const float* __restrict__ bias,
    float* __restrict__ out)
{
    float* wsm  = (float*)sm;                  // [64ch][64oc] 16384 B
    float* colT = (float*)(sm + 16384);        // [64ch][CST2] 33792 B

    const int tid = threadIdx.x;

    // ---- wait for this row's offsets/masks ----
    if (tid == 0) {
        int* fp = &g_flag[b * 64 + (h >> 1)];
        while (atomicAdd(fp, 0) < 2) { __nanosleep(200); }
    }
    __syncthreads();
    __threadfence();

    const float* dbase = data + (size_t)b * CIN * HW;
    const float* omb   = g_om + ((size_t)(b * NCH) * HH + h) * WW;

    // GEMM mapping: 8 oc (i) x 8 px (j: j*4 and 64+j*4)
    const int i   = tid >> 4;            // 0..7
    const int j   = tid & 15;            // 0..15
    const int oc0 = i * 8;

    const int x = tid;                   // gather pixel = tid (0..127)

    uint64_t acc[4][8];                  // [oc pair][px 0..3, 64+0..3]
#pragma unroll
    for (int p = 0; p < 4; p++)
#pragma unroll
        for (int q = 0; q < 8; q++) acc[p][q] = 0ULL;

    for (int t = 0; t < 9; t++) {
        __syncthreads();                 // prev GEMM done before overwrite

        // ---- stage this tap's weights (16KB, float4, coalesced) ----
        {
            const float4* wsrc = (const float4*)(g_wT + t * 4096);
            float4* wdst = (float4*)wsm;
#pragma unroll
            for (int r = 0; r < 8; r++) wdst[tid + r * 128] = wsrc[tid + r * 128];
        }

        // ---- bilinear metadata for this thread's pixel ----
        const float dy = omb[(2 * t) * HW + x];
        const float dx = omb[(2 * t + 1) * HW + x];
        const float mk = omb[(18 + t) * HW + x];

        const float py = (float)(h - 1 + t / 3) + dy;
        const float px = (float)(x - 1 + t % 3) + dx;

        const float y0f = floorf(py), x0f = floorf(px);
        const float wy1 = py - y0f,  wx1 = px - x0f;
        const float wy0 = 1.0f - wy1, wx0 = 1.0f - wx1;

        const int y0 = (int)y0f, x0 = (int)x0f;
        const int y1 = y0 + 1,   x1 = x0 + 1;
        const bool vy0 = (y0 >= 0) && (y0 < HH);
        const bool vy1 = (y1 >= 0) && (y1 < HH);
        const bool vx0 = (x0 >= 0) && (x0 < WW);
        const bool vx1 = (x1 >= 0) && (x1 < WW);

        const float w00 = (vy0 && vx0) ? mk * wy0 * wx0 : 0.0f;
        const float w01 = (vy0 && vx1) ? mk * wy0 * wx1 : 0.0f;
        const float w10 = (vy1 && vx0) ? mk * wy1 * wx0 : 0.0f;
        const float w11 = (vy1 && vx1) ? mk * wy1 * wx1 : 0.0f;

        const int yc0 = min(max(y0, 0), HH - 1);
        const int yc1 = min(max(y1, 0), HH - 1);
        const int xc0 = min(max(x0, 0), WW - 1);
        const int xc1 = min(max(x1, 0), WW - 1);
        const int i00 = yc0 * WW + xc0;
        const int i01 = yc0 * WW + xc1;
        const int i10 = yc1 * WW + xc0;
        const int i11 = yc1 * WW + xc1;

        // ---- gather all 64 channels for this pixel ----
        const float* d2 = dbase;
        float* cp = colT + x;
#pragma unroll 8
        for (int cc = 0; cc < 64; cc++) {
            float v = w00 * d2[i00];
            v = fmaf(w01, d2[i01], v);
            v = fmaf(w10, d2[i10], v);
            v = fmaf(w11, d2[i11], v);
            cp[cc * CST2] = v;
            d2 += HW;
        }
        __syncthreads();

        // ---- GEMM: 64 k for this tap; weights via broadcast LDS ----
        const float* wrow = wsm + oc0;
        const float* crow = colT + j * 4;
#pragma unroll 8
        for (int kl = 0; kl < 64; kl++) {
            ulonglong2 wA = *(const ulonglong2*)(wrow + kl * 64);      // oc pairs 0,1
            ulonglong2 wB = *(const ulonglong2*)(wrow + kl * 64 + 4);  // oc pairs 2,3
            float4 cv1 = *(const float4*)(crow + kl * CST2);           // px j4..j4+3
            float4 cv2 = *(const float4*)(crow + kl * CST2 + 64);      // px 64+j4..
            uint64_t c0 = pack2(cv1.x, cv1.x);
            uint64_t c1 = pack2(cv1.y, cv1.y);
            uint64_t c2 = pack2(cv1.z, cv1.z);
            uint64_t c3 = pack2(cv1.w, cv1.w);
            uint64_t c4 = pack2(cv2.x, cv2.x);
            uint64_t c5 = pack2(cv2.y, cv2.y);
            uint64_t c6 = pack2(cv2.z, cv2.z);
            uint64_t c7 = pack2(cv2.w, cv2.w);
            FFMA2(acc[0][0], wA.x, c0); FFMA2(acc[0][1], wA.x, c1);
            FFMA2(acc[0][2], wA.x, c2); FFMA2(acc[0][3], wA.x, c3);
            FFMA2(acc[0][4], wA.x, c4); FFMA2(acc[0][5], wA.x, c5);
            FFMA2(acc[0][6], wA.x, c6); FFMA2(acc[0][7], wA.x, c7);
            FFMA2(acc[1][0], wA.y, c0); FFMA2(acc[1][1], wA.y, c1);
            FFMA2(acc[1][2], wA.y, c2); FFMA2(acc[1][3], wA.y, c3);
            FFMA2(acc[1][4], wA.y, c4); FFMA2(acc[1][5], wA.y, c5);
            FFMA2(acc[1][6], wA.y, c6); FFMA2(acc[1][7], wA.y, c7);
            FFMA2(acc[2][0], wB.x, c0); FFMA2(acc[2][1], wB.x, c1);
            FFMA2(acc[2][2], wB.x, c2); FFMA2(acc[2][3], wB.x, c3);
            FFMA2(acc[2][4], wB.x, c4); FFMA2(acc[2][5], wB.x, c5);
            FFMA2(acc[2][6], wB.x, c6); FFMA2(acc[2][7], wB.x, c7);
            FFMA2(acc[3][0], wB.y, c0); FFMA2(acc[3][1], wB.y, c1);
            FFMA2(acc[3][2], wB.y, c2); FFMA2(acc[3][3], wB.y, c3);
            FFMA2(acc[3][4], wB.y, c4); FFMA2(acc[3][5], wB.y, c5);
            FFMA2(acc[3][6], wB.y, c6); FFMA2(acc[3][7], wB.y, c7);
        }
    }

    // ---- epilogue: bias + relu + float4 stores (2 groups of 4 px) ----
#pragma unroll
    for (int p = 0; p < 4; p++) {
        const int ocA = oc0 + 2 * p;
        const float bA = bias[ocA];
        const float bB = bias[ocA + 1];
        float* obA = out + (((size_t)(b * COUT + ocA)) * HH + h) * WW;
        float a0, b0, a1, b1, a2, b2, a3, b3;
        unpack2(acc[p][0], a0, b0);
        unpack2(acc[p][1], a1, b1);
        unpack2(acc[p][2], a2, b2);
        unpack2(acc[p][3], a3, b3);
        {
            float4 rA = make_float4(fmaxf(a0 + bA, 0.f), fmaxf(a1 + bA, 0.f),
                                    fmaxf(a2 + bA, 0.f), fmaxf(a3 + bA, 0.f));
            *(float4*)(obA + j * 4) = rA;
            float4 rB = make_float4(fmaxf(b0 + bB, 0.f), fmaxf(b1 + bB, 0.f),
                                    fmaxf(b2 + bB, 0.f), fmaxf(b3 + bB, 0.f));
            *(float4*)(obA + HW + j * 4) = rB;
        }
        unpack2(acc[p][4], a0, b0);
        unpack2(acc[p][5], a1, b1);
        unpack2(acc[p][6], a2, b2);
        unpack2(acc[p][7], a3, b3);
        {
            float4 rA = make_float4(fmaxf(a0 + bA, 0.f), fmaxf(a1 + bA, 0.f),
                                    fmaxf(a2 + bA, 0.f), fmaxf(a3 + bA, 0.f));
            *(float4*)(obA + 64 + j * 4) = rA;
            float4 rB = make_float4(fmaxf(b0 + bB, 0.f), fmaxf(b1 + bB, 0.f),
                                    fmaxf(b2 + bB, 0.f), fmaxf(b3 + bB, 0.f));
            *(float4*)(obA + HW + 64 + j * 4) = rB;
        }
    }
}

// ---------------------------------------------------------------------------
// Fused kernel: bids [0,1024) conv, [1024,2048) deform (full-row blocks).
// ---------------------------------------------------------------------------
__global__ void __launch_bounds__(128, 4) fused_kernel2(
    const float* __restrict__ data,
    const float* __restrict__ w_off, const float* __restrict__ b_off,
    const float* __restrict__ w_mod, const float* __restrict__ b_mod,
    const float* __restrict__ bias,
    float* __restrict__ out)
{
    extern __shared__ char sm[];
    const int bid = blockIdx.x;
    if (bid < CONV_BLOCKS) {
        const int hp = bid & 63;
        const int b  = (bid >> 6) & 7;
        const int z  = bid >> 9;
        conv_role(sm, b, hp | (z << 6), data, w_off, b_off, w_mod, b_mod);
    } else {
        const int idx = bid - CONV_BLOCKS;
        deform_role(sm, idx >> 7, idx & 127, data, bias, out);
    }
}

// ---------------------------------------------------------------------------
extern "C" void kernel_launch(void* const* d_in, const int* in_sizes, int n_in,
                              void* d_out, int out_size)
{
    const float* data  = (const float*)d_in[0];
    const float* w     = (const float*)d_in[1];
    const float* bias  = (const float*)d_in[2];
    const float* w_off = (const float*)d_in[3];
    const float* b_off = (const float*)d_in[4];
    const float* w_mod = (const float*)d_in[5];
    const float* b_mod = (const float*)d_in[6];
    float* out = (float*)d_out;

    void* flag_ptr = nullptr;
    cudaGetSymbolAddress(&flag_ptr, g_flag);
    cudaMemsetAsync(flag_ptr, 0, BB * 64 * sizeof(int));

    cudaFuncSetAttribute(fused_kernel2,
                         cudaFuncAttributeMaxDynamicSharedMemorySize, FSM_BYTES);

    transpose_w_kernel<<<144, 256>>>(w);
    fused_kernel2<<<CONV_BLOCKS + DEF_BLOCKS, 128, FSM_BYTES>>>(
        data, w_off, b_off, w_mod, b_mod, bias, out);
}

// round 16
// speedup vs baseline: 1.2142x; 1.0304x over previous
#include <cuda_runtime.h>
#include <math.h>
#include <stdint.h>

#define HH 128
#define WW 128
#define BB 8
#define CIN 64
#define COUT 64
#define HW (HH*WW)
#define NCH 27            // 18 offset channels + 9 mask channels
#define NPAIR 7
#define CST2 132          // colT row stride in floats (128 + 4 pad)

// scratch (allocation-free: device globals)
__device__ float g_om[BB*NCH*HW];     // offsets + mask=2*sigmoid
__device__ float g_wT[9*64*64];       // [tap][cin][oc]
__device__ int   g_flag[BB*64];       // per (b, row-pair) completion count (0..2)

#define CONV_BLOCKS 512               // (32 hq) x (8 b) x (2 z), 4 rows each
#define DEF_BLOCKS  1024              // (8 b) x (128 h), full row per block
#define FSM_BYTES 50176               // max(conv 43264, deform 16384+33792)

// ---------------------------------------------------------------------------
// packed fp32x2 helpers
// ---------------------------------------------------------------------------
__device__ __forceinline__ uint64_t pack2(float lo, float hi) {
    uint64_t r;
    asm("mov.b64 %0, {%1,%2};" : "=l"(r)
        : "r"(__float_as_uint(lo)), "r"(__float_as_uint(hi)));
    return r;
}
__device__ __forceinline__ void unpack2(uint64_t v, float& lo, float& hi) {
    uint32_t a, b;
    asm("mov.b64 {%0,%1}, %2;" : "=r"(a), "=r"(b) : "l"(v));
    lo = __uint_as_float(a); hi = __uint_as_float(b);
}
#define FFMA2(acc, a, b) \
    asm("fma.rn.f32x2 %0, %1, %2, %0;" : "+l"(acc) : "l"(a), "l"(b))

// ---------------------------------------------------------------------------
// Kernel 0: weight transform [oc][c][3][3] -> g_wT[t][c][oc]
// ---------------------------------------------------------------------------
__global__ void transpose_w_kernel(const float* __restrict__ w) {
    int idx = blockIdx.x * 256 + threadIdx.x;
    if (idx < 576 * COUT) {
        int oc  = idx / 576;
        int rem = idx % 576;
        int c   = rem / 9;
        int t   = rem % 9;
        g_wT[t * 4096 + c * 64 + oc] = w[idx];
    }
}

// ---------------------------------------------------------------------------
// Conv role: 4 output rows per block (R9 body — halved weight-LDS traffic).
// (b, c): hq = c & 31, z = c >> 5. Writes g_om rows 4hq..4hq+3; signals
// both row-pair flags.
// ---------------------------------------------------------------------------
__device__ __forceinline__ void conv_role(
    char* sm, int b, int c,
    const float* __restrict__ data,
    const float* __restrict__ w_off, const float* __restrict__ b_off,
    const float* __restrict__ w_mod, const float* __restrict__ b_mod)
{
    uint64_t* wsp   = (uint64_t*)sm;                 // 17920 B
    float*    dtile = (float*)(sm + 17920);          // 8*6*132*4 = 25344 B

    const int hq = c & 31;
    const int pb = (c >> 5) * NPAIR;                 // pair base (0 or 7)
    const int h0 = hq * 4;
    const int x  = threadIdx.x;

    // zero halo columns (cells 0 and 129 of each of 8ch x 6 rows)
    if (threadIdx.x < 96) {
        int q = threadIdx.x / 12;
        int r = (threadIdx.x % 12) >> 1;
        int s = threadIdx.x & 1;
        dtile[q * 792 + r * 132 + s * 129] = 0.0f;
    }

    uint64_t acc2[4][NPAIR];
#pragma unroll
    for (int p = 0; p < NPAIR; p++) {
        int ocA = 2 * (pb + p), ocB = ocA + 1;
        float bA = (ocA < 18) ? b_off[ocA] : b_mod[ocA - 18];
        float bB = (ocB < 18) ? b_off[ocB] : ((ocB < 27) ? b_mod[ocB - 18] : 0.0f);
        acc2[0][p] = pack2(bA, bB);
        acc2[1][p] = acc2[0][p];
        acc2[2][p] = acc2[0][p];
        acc2[3][p] = acc2[0][p];
    }

    for (int c0 = 0; c0 < CIN; c0 += 32) {
        __syncthreads();
        for (int idx = threadIdx.x; idx < NPAIR * 32 * 9; idx += 128) {
            int p  = idx / 288;
            int r  = idx % 288;
            int cc = r / 9;
            int k  = r % 9;
            int ocA = 2 * (pb + p), ocB = ocA + 1;
            const float* sA = (ocA < 18) ? (w_off + ocA * 576) : (w_mod + (ocA - 18) * 576);
            float vA = sA[(c0 + cc) * 9 + k];
            float vB = 0.0f;
            if (ocB < 27) {
                const float* sB = (ocB < 18) ? (w_off + ocB * 576) : (w_mod + (ocB - 18) * 576);
                vB = sB[(c0 + cc) * 9 + k];
            }
            wsp[(p * 32 + cc) * 10 + k] = pack2(vA, vB);
        }

        for (int cg = 0; cg < 4; cg++) {
            __syncthreads();
            const int cb = c0 + cg * 8;
#pragma unroll
            for (int q = 0; q < 8; q++) {
                const float* dp = data + ((size_t)(b * CIN + cb + q)) * HW;
#pragma unroll
                for (int r = 0; r < 6; r++) {
                    int hy = h0 - 1 + r;
                    float v = 0.0f;
                    if (hy >= 0 && hy < HH) v = dp[hy * WW + x];
                    dtile[q * 792 + r * 132 + 1 + x] = v;
                }
            }
            __syncthreads();

#pragma unroll
            for (int q = 0; q < 8; q++) {
                const int cc = cg * 8 + q;
                const float* dp = dtile + q * 792 + x;
                uint64_t dup[6][3];
#pragma unroll
                for (int r = 0; r < 6; r++)
#pragma unroll
                    for (int kx = 0; kx < 3; kx++) {
                        float v = dp[r * 132 + kx];
                        dup[r][kx] = pack2(v, v);
                    }

#pragma unroll
                for (int p = 0; p < NPAIR; p++) {
                    const uint64_t* base = wsp + (p * 32 + cc) * 10;
                    ulonglong2 w01 = *(const ulonglong2*)(base + 0);
                    ulonglong2 w23 = *(const ulonglong2*)(base + 2);
                    ulonglong2 w45 = *(const ulonglong2*)(base + 4);
                    ulonglong2 w67 = *(const ulonglong2*)(base + 6);
                    uint64_t   w8  = base[8];
#pragma unroll
                    for (int rr = 0; rr < 4; rr++) {
                        FFMA2(acc2[rr][p], dup[rr + 0][0], w01.x);
                        FFMA2(acc2[rr][p], dup[rr + 0][1], w01.y);
                        FFMA2(acc2[rr][p], dup[rr + 0][2], w23.x);
                        FFMA2(acc2[rr][p], dup[rr + 1][0], w23.y);
                        FFMA2(acc2[rr][p], dup[rr + 1][1], w45.x);
                        FFMA2(acc2[rr][p], dup[rr + 1][2], w45.y);
                        FFMA2(acc2[rr][p], dup[rr + 2][0], w67.x);
                        FFMA2(acc2[rr][p], dup[rr + 2][1], w67.y);
                        FFMA2(acc2[rr][p], dup[rr + 2][2], w8);
                    }
                }
            }
        }
    }

#pragma unroll
    for (int rr = 0; rr < 4; rr++) {
        float* outp = g_om + ((size_t)(b * NCH) * HH + (h0 + rr)) * WW + x;
#pragma unroll
        for (int p = 0; p < NPAIR; p++) {
            float lo, hi;
            unpack2(acc2[rr][p], lo, hi);
            int ocA = 2 * (pb + p), ocB = ocA + 1;
            if (ocA >= 18) lo = 2.0f / (1.0f + expf(-lo));
            outp[ocA * HW] = lo;
            if (ocB < 27) {
                if (ocB >= 18) hi = 2.0f / (1.0f + expf(-hi));
                outp[ocB * HW] = hi;
            }
        }
    }

    __syncthreads();
    __threadfence();
    if (threadIdx.x == 0) {
        atomicAdd(&g_flag[b * 64 + hq * 2], 1);
        atomicAdd(&g_flag[b * 64 + hq * 2 + 1], 1);
    }
}

// ---------------------------------------------------------------------------
// Deform role (R15 body, measured best): full 128-px row per block, weights
// staged in smem per tap. smem = 16KB + 33.8KB; regs 128.
// ---------------------------------------------------------------------------
__device__ __forceinline__ void deform_role(
    char* sm, int b, int h,
    const float* __restrict__ data,
    const float* __restrict__ bias,
    float* __restrict__ out)
{
    float* wsm  = (float*)sm;                  // [64ch][64oc] 16384 B
    float* colT = (float*)(sm + 16384);        // [64ch][CST2] 33792 B

    const int tid = threadIdx.x;

    // ---- wait for this row's offsets/masks ----
    if (tid == 0) {
        int* fp = &g_flag[b * 64 + (h >> 1)];
        while (atomicAdd(fp, 0) < 2) { __nanosleep(200); }
    }
    __syncthreads();
    __threadfence();

    const float* dbase = data + (size_t)b * CIN * HW;
    const float* omb   = g_om + ((size_t)(b * NCH) * HH + h) * WW;

    const int i   = tid >> 4;            // 0..7
    const int j   = tid & 15;            // 0..15
    const int oc0 = i * 8;

    const int x = tid;                   // gather pixel = tid (0..127)

    uint64_t acc[4][8];                  // [oc pair][px 0..3, 64+0..3]
#pragma unroll
    for (int p = 0; p < 4; p++)
#pragma unroll
        for (int q = 0; q < 8; q++) acc[p][q] = 0ULL;

    for (int t = 0; t < 9; t++) {
        __syncthreads();                 // prev GEMM done before overwrite

        // ---- stage this tap's weights (16KB, float4, coalesced) ----
        {
            const float4* wsrc = (const float4*)(g_wT + t * 4096);
            float4* wdst = (float4*)wsm;
#pragma unroll
            for (int r = 0; r < 8; r++) wdst[tid + r * 128] = wsrc[tid + r * 128];
        }

        // ---- bilinear metadata for this thread's pixel ----
        const float dy = omb[(2 * t) * HW + x];
        const float dx = omb[(2 * t + 1) * HW + x];
        const float mk = omb[(18 + t) * HW + x];

        const float py = (float)(h - 1 + t / 3) + dy;
        const float px = (float)(x - 1 + t % 3) + dx;

        const float y0f = floorf(py), x0f = floorf(px);
        const float wy1 = py - y0f,  wx1 = px - x0f;
        const float wy0 = 1.0f - wy1, wx0 = 1.0f - wx1;

        const int y0 = (int)y0f, x0 = (int)x0f;
        const int y1 = y0 + 1,   x1 = x0 + 1;
        const bool vy0 = (y0 >= 0) && (y0 < HH);
        const bool vy1 = (y1 >= 0) && (y1 < HH);
        const bool vx0 = (x0 >= 0) && (x0 < WW);
        const bool vx1 = (x1 >= 0) && (x1 < WW);

        const float w00 = (vy0 && vx0) ? mk * wy0 * wx0 : 0.0f;
        const float w01 = (vy0 && vx1) ? mk * wy0 * wx1 : 0.0f;
        const float w10 = (vy1 && vx0) ? mk * wy1 * wx0 : 0.0f;
        const float w11 = (vy1 && vx1) ? mk * wy1 * wx1 : 0.0f;

        const int yc0 = min(max(y0, 0), HH - 1);
        const int yc1 = min(max(y1, 0), HH - 1);
        const int xc0 = min(max(x0, 0), WW - 1);
        const int xc1 = min(max(x1, 0), WW - 1);
        const int i00 = yc0 * WW + xc0;
        const int i01 = yc0 * WW + xc1;
        const int i10 = yc1 * WW + xc0;
        const int i11 = yc1 * WW + xc1;

        // ---- gather all 64 channels for this pixel ----
        const float* d2 = dbase;
        float* cp = colT + x;
#pragma unroll 8
        for (int cc = 0; cc < 64; cc++) {
            float v = w00 * d2[i00];
            v = fmaf(w01, d2[i01], v);
            v = fmaf(w10, d2[i10], v);
            v = fmaf(w11, d2[i11], v);
            cp[cc * CST2] = v;
            d2 += HW;
        }
        __syncthreads();

        // ---- GEMM: 64 k for this tap; weights via broadcast LDS ----
        const float* wrow = wsm + oc0;
        const float* crow = colT + j * 4;
#pragma unroll 8
        for (int kl = 0; kl < 64; kl++) {
            ulonglong2 wA = *(const ulonglong2*)(wrow + kl * 64);      // oc pairs 0,1
            ulonglong2 wB = *(const ulonglong2*)(wrow + kl * 64 + 4);  // oc pairs 2,3
            float4 cv1 = *(const float4*)(crow + kl * CST2);           // px j4..j4+3
            float4 cv2 = *(const float4*)(crow + kl * CST2 + 64);      // px 64+j4..
            uint64_t c0 = pack2(cv1.x, cv1.x);
            uint64_t c1 = pack2(cv1.y, cv1.y);
            uint64_t c2 = pack2(cv1.z, cv1.z);
            uint64_t c3 = pack2(cv1.w, cv1.w);
            uint64_t c4 = pack2(cv2.x, cv2.x);
            uint64_t c5 = pack2(cv2.y, cv2.y);
            uint64_t c6 = pack2(cv2.z, cv2.z);
            uint64_t c7 = pack2(cv2.w, cv2.w);
            FFMA2(acc[0][0], wA.x, c0); FFMA2(acc[0][1], wA.x, c1);
            FFMA2(acc[0][2], wA.x, c2); FFMA2(acc[0][3], wA.x, c3);
            FFMA2(acc[0][4], wA.x, c4); FFMA2(acc[0][5], wA.x, c5);
            FFMA2(acc[0][6], wA.x, c6); FFMA2(acc[0][7], wA.x, c7);
            FFMA2(acc[1][0], wA.y, c0); FFMA2(acc[1][1], wA.y, c1);
            FFMA2(acc[1][2], wA.y, c2); FFMA2(acc[1][3], wA.y, c3);
            FFMA2(acc[1][4], wA.y, c4); FFMA2(acc[1][5], wA.y, c5);
            FFMA2(acc[1][6], wA.y, c6); FFMA2(acc[1][7], wA.y, c7);
            FFMA2(acc[2][0], wB.x, c0); FFMA2(acc[2][1], wB.x, c1);
            FFMA2(acc[2][2], wB.x, c2); FFMA2(acc[2][3], wB.x, c3);
            FFMA2(acc[2][4], wB.x, c4); FFMA2(acc[2][5], wB.x, c5);
            FFMA2(acc[2][6], wB.x, c6); FFMA2(acc[2][7], wB.x, c7);
            FFMA2(acc[3][0], wB.y, c0); FFMA2(acc[3][1], wB.y, c1);
            FFMA2(acc[3][2], wB.y, c2); FFMA2(acc[3][3], wB.y, c3);
            FFMA2(acc[3][4], wB.y, c4); FFMA2(acc[3][5], wB.y, c5);
            FFMA2(acc[3][6], wB.y, c6); FFMA2(acc[3][7], wB.y, c7);
        }
    }

    // ---- epilogue: bias + relu + float4 stores (2 groups of 4 px) ----
#pragma unroll
    for (int p = 0; p < 4; p++) {
        const int ocA = oc0 + 2 * p;
        const float bA = bias[ocA];
        const float bB = bias[ocA + 1];
        float* obA = out + (((size_t)(b * COUT + ocA)) * HH + h) * WW;
        float a0, b0, a1, b1, a2, b2, a3, b3;
        unpack2(acc[p][0], a0, b0);
        unpack2(acc[p][1], a1, b1);
        unpack2(acc[p][2], a2, b2);
        unpack2(acc[p][3], a3, b3);
        {
            float4 rA = make_float4(fmaxf(a0 + bA, 0.f), fmaxf(a1 + bA, 0.f),
                                    fmaxf(a2 + bA, 0.f), fmaxf(a3 + bA, 0.f));
            *(float4*)(obA + j * 4) = rA;
            float4 rB = make_float4(fmaxf(b0 + bB, 0.f), fmaxf(b1 + bB, 0.f),
                                    fmaxf(b2 + bB, 0.f), fmaxf(b3 + bB, 0.f));
            *(float4*)(obA + HW + j * 4) = rB;
        }
        unpack2(acc[p][4], a0, b0);
        unpack2(acc[p][5], a1, b1);
        unpack2(acc[p][6], a2, b2);
        unpack2(acc[p][7], a3, b3);
        {
            float4 rA = make_float4(fmaxf(a0 + bA, 0.f), fmaxf(a1 + bA, 0.f),
                                    fmaxf(a2 + bA, 0.f), fmaxf(a3 + bA, 0.f));
            *(float4*)(obA + 64 + j * 4) = rA;
            float4 rB = make_float4(fmaxf(b0 + bB, 0.f), fmaxf(b1 + bB, 0.f),
                                    fmaxf(b2 + bB, 0.f), fmaxf(b3 + bB, 0.f));
            *(float4*)(obA + HW + 64 + j * 4) = rB;
        }
    }
}

// ---------------------------------------------------------------------------
// Fused kernel: bids [0,512) conv (4-row), [512,1536) deform (full-row).
// ---------------------------------------------------------------------------
__global__ void __launch_bounds__(128, 4) fused_kernel3(
    const float* __restrict__ data,
    const float* __restrict__ w_off, const float* __restrict__ b_off,
    const float* __restrict__ w_mod, const float* __restrict__ b_mod,
    const float* __restrict__ bias,
    float* __restrict__ out)
{
    extern __shared__ char sm[];
    const int bid = blockIdx.x;
    if (bid < CONV_BLOCKS) {
        const int hq = bid & 31;
        const int b  = (bid >> 5) & 7;
        const int z  = bid >> 8;
        conv_role(sm, b, hq | (z << 5), data, w_off, b_off, w_mod, b_mod);
    } else {
        const int idx = bid - CONV_BLOCKS;
        deform_role(sm, idx >> 7, idx & 127, data, bias, out);
    }
}

// ---------------------------------------------------------------------------
extern "C" void kernel_launch(void* const* d_in, const int* in_sizes, int n_in,
                              void* d_out, int out_size)
{
    const float* data  = (const float*)d_in[0];
    const float* w     = (const float*)d_in[1];
    const float* bias  = (const float*)d_in[2];
    const float* w_off = (const float*)d_in[3];
    const float* b_off = (const float*)d_in[4];
    const float* w_mod = (const float*)d_in[5];
    const float* b_mod = (const float*)d_in[6];
    float* out = (float*)d_out;

    void* flag_ptr = nullptr;
    cudaGetSymbolAddress(&flag_ptr, g_flag);
    cudaMemsetAsync(flag_ptr, 0, BB * 64 * sizeof(int));

    cudaFuncSetAttribute(fused_kernel3,
                         cudaFuncAttributeMaxDynamicSharedMemorySize, FSM_BYTES);

    transpose_w_kernel<<<144, 256>>>(w);
    fused_kernel3<<<CONV_BLOCKS + DEF_BLOCKS, 128, FSM_BYTES>>>(
        data, w_off, b_off, w_mod, b_mod, bias, out);
}